// round 14
// baseline (speedup 1.0000x reference)
#include <cuda_runtime.h>
#include <cuda_bf16.h>
#include <math.h>
#include <stdint.h>

#define BATCH 2
#define CCH 512
#define NH 8
#define HD 64
#define GROUPS 32
#define NTOK 4096
#define EPS 1e-5f
#define LOG2E 1.44269504f
#define SOFF -8.0f   // static softmax offset (log2 units); logits |c|<~4, safe

// ---------------- scratch (static device globals; no allocation) -------------
__device__ __nv_bfloat16 g_hn[(size_t)BATCH * CCH * NTOK];          // 8 MB
__device__ __nv_bfloat16 g_qkv[(size_t)BATCH * 3 * CCH * NTOK];     // 25 MB
__device__ __nv_bfloat16 g_aoT[(size_t)BATCH * NTOK * CCH];         // 8 MB [b][n][c]
__device__ __nv_bfloat16 g_qkvwb[3 * CCH * CCH];                    // 1.5 MB
__device__ __nv_bfloat16 g_projwb[CCH * CCH];                       // 0.5 MB

// ---------------- helpers -----------------------------------------------------
__device__ __forceinline__ uint32_t packb(float lo, float hi) {
    __nv_bfloat162 t = __floats2bfloat162_rn(lo, hi);
    return *(uint32_t*)&t;
}
__device__ __forceinline__ uint32_t ex2b(float lo, float hi) {
    __nv_bfloat162 t = __floats2bfloat162_rn(lo, hi);
    uint32_t u = *(uint32_t*)&t, y;
    asm("ex2.approx.ftz.bf16x2 %0, %1;" : "=r"(y) : "r"(u));
    return y;
}
__device__ __forceinline__ void mma_bf16(float c[4], const uint32_t a[4],
                                         uint32_t b0, uint32_t b1) {
    asm volatile(
        "mma.sync.aligned.m16n8k16.row.col.f32.bf16.bf16.f32 "
        "{%0,%1,%2,%3}, {%4,%5,%6,%7}, {%8,%9}, {%0,%1,%2,%3};\n"
        : "+f"(c[0]), "+f"(c[1]), "+f"(c[2]), "+f"(c[3])
        : "r"(a[0]), "r"(a[1]), "r"(a[2]), "r"(a[3]), "r"(b0), "r"(b1));
}
__device__ __forceinline__ void ldsm4t(uint32_t r[4], uint32_t addr) {
    asm volatile(
        "ldmatrix.sync.aligned.m8n8.x4.trans.shared.b16 {%0,%1,%2,%3}, [%4];"
        : "=r"(r[0]), "=r"(r[1]), "=r"(r[2]), "=r"(r[3]) : "r"(addr));
}
__device__ __forceinline__ void ldsm4(uint32_t r[4], uint32_t addr) {
    asm volatile(
        "ldmatrix.sync.aligned.m8n8.x4.shared.b16 {%0,%1,%2,%3}, [%4];"
        : "=r"(r[0]), "=r"(r[1]), "=r"(r[2]), "=r"(r[3]) : "r"(addr));
}
#define CP_ASYNC16(dst, src) \
    asm volatile("cp.async.cg.shared.global [%0], [%1], 16;" :: "r"(dst), "l"(src))
#define CP_COMMIT() asm volatile("cp.async.commit_group;")
#define CP_WAIT0() asm volatile("cp.async.wait_group 0;")
#define CP_WAIT1() asm volatile("cp.async.wait_group 1;")

// ---------------- weight conversion fp32 -> bf16 ------------------------------
__global__ void cvt_w(const float* __restrict__ qkv_w, const float* __restrict__ proj_w) {
    const int NQ = 3 * CCH * CCH / 4;
    int i = blockIdx.x * 256 + threadIdx.x;
    if (i < NQ) {
        float4 v = ((const float4*)qkv_w)[i];
        uint2 o; o.x = packb(v.x, v.y); o.y = packb(v.z, v.w);
        ((uint2*)g_qkvwb)[i] = o;
    } else {
        int j = i - NQ;
        float4 v = ((const float4*)proj_w)[j];
        uint2 o; o.x = packb(v.x, v.y); o.y = packb(v.z, v.w);
        ((uint2*)g_projwb)[j] = o;
    }
}

// ---------------- GroupNorm: fused single kernel ------------------------------
__global__ void __launch_bounds__(512)
gn_fused(const float* __restrict__ x,
         const float* __restrict__ w,
         const float* __restrict__ b) {
    const int bg = blockIdx.x;
    const int g = bg % GROUPS;
    const int tid = threadIdx.x;
    const float4* xp = (const float4*)x + (size_t)bg * 16384;
    uint2* hp = (uint2*)(g_hn + (size_t)bg * 65536);

    float s = 0.f, s2 = 0.f;
#pragma unroll 8
    for (int i = tid; i < 16384; i += 512) {
        float4 v = xp[i];
        s += v.x + v.y + v.z + v.w;
        s2 += v.x * v.x + v.y * v.y + v.z * v.z + v.w * v.w;
    }
    __shared__ float sh[512], sh2[512];
    sh[tid] = s; sh2[tid] = s2;
    __syncthreads();
    for (int o = 256; o > 0; o >>= 1) {
        if (tid < o) { sh[tid] += sh[tid + o]; sh2[tid] += sh2[tid + o]; }
        __syncthreads();
    }
    float mean = sh[0] / 65536.f;
    float var  = sh2[0] / 65536.f - mean * mean;
    float inv  = rsqrtf(var + EPS);

#pragma unroll 8
    for (int i = tid; i < 16384; i += 512) {
        int ch = g * 16 + (i >> 10);
        float sc = inv * w[ch];
        float off = b[ch] - mean * sc;
        float4 v = xp[i];
        uint2 o;
        o.x = packb(v.x * sc + off, v.y * sc + off);
        o.y = packb(v.z * sc + off, v.w * sc + off);
        hp[i] = o;
    }
}

// ---------------- bf16 GEMM (best measured): cp.async, BK=32, 3-stage ---------
#define ASTG 10240   // 128*40*2
#define BSTG0 8704   // 32*136*2
#define BSTG1 10240  // 128*40*2
template <int MODE>
__global__ void __launch_bounds__(256, 2)
gemm3(const __nv_bfloat16* __restrict__ A, const __nv_bfloat16* __restrict__ B,
      void* __restrict__ Cv, int lda, int ldb, int ldc,
      size_t sB, size_t sC,
      const float* __restrict__ bias,
      const float* __restrict__ resid, size_t sR) {
    constexpr int BSTG = (MODE == 0) ? BSTG0 : BSTG1;
    extern __shared__ __align__(16) char gsm[];
    const uint32_t asmb = (uint32_t)__cvta_generic_to_shared(gsm);
    const uint32_t bsmb = asmb + 3 * ASTG;

    const int tid = threadIdx.x;
    const int w = tid >> 5, lane = tid & 31;
    const int g = lane >> 2, tg = lane & 3;
    const int wm = w >> 2, wn = w & 3;
    const int m0 = blockIdx.y * 128;
    const int n0 = blockIdx.x * 128;

    B += (size_t)blockIdx.z * sB;
    float* Cf = (float*)Cv + (MODE == 1 ? (size_t)blockIdx.z * sC : 0);
    __nv_bfloat16* Ch = (__nv_bfloat16*)Cv + (MODE == 0 ? (size_t)blockIdx.z * sC : 0);
    if (MODE == 1 && resid) resid += (size_t)blockIdx.z * sR;

    int ar[2], ac[2], br[2], bc[2];
    uint32_t adst[2], bdst[2];
#pragma unroll
    for (int i = 0; i < 2; i++) {
        int e = tid + i * 256;
        ar[i] = e >> 2; ac[i] = (e & 3) * 8;
        adst[i] = asmb + (uint32_t)((ar[i] * 40 + ac[i]) * 2);
        if (MODE == 0) {
            br[i] = e >> 4; bc[i] = (e & 15) * 8;
            bdst[i] = bsmb + (uint32_t)((br[i] * 136 + bc[i]) * 2);
        } else {
            br[i] = e >> 2; bc[i] = (e & 3) * 8;
            bdst[i] = bsmb + (uint32_t)((br[i] * 40 + bc[i]) * 2);
        }
    }

#define G3_ISSUE(kk, st)                                                        \
    do {                                                                        \
        _Pragma("unroll")                                                       \
        for (int i = 0; i < 2; i++) {                                           \
            CP_ASYNC16(adst[i] + (st) * ASTG,                                   \
                       &A[(size_t)(m0 + ar[i]) * lda + (kk) + ac[i]]);          \
            if (MODE == 0)                                                      \
                CP_ASYNC16(bdst[i] + (st) * BSTG,                               \
                           &B[(size_t)((kk) + br[i]) * ldb + n0 + bc[i]]);      \
            else                                                                \
                CP_ASYNC16(bdst[i] + (st) * BSTG,                               \
                           &B[(size_t)(n0 + br[i]) * ldb + (kk) + bc[i]]);      \
        }                                                                       \
        CP_COMMIT();                                                            \
    } while (0)

    G3_ISSUE(0, 0);
    G3_ISSUE(32, 1);

    const uint32_t afrag = asmb + (uint32_t)((lane & 15) * 80 + (lane >> 4) * 16);
    uint32_t bfrag;
    if (MODE == 0)
        bfrag = bsmb + (uint32_t)((((lane >> 3 & 1) * 8) + (lane & 7)) * 272 + (lane >> 4) * 16);
    else
        bfrag = bsmb + (uint32_t)((lane & 7) * 80 + (lane >> 3) * 16);

    float acc[4][4][4];
#pragma unroll
    for (int mf = 0; mf < 4; mf++)
#pragma unroll
        for (int nf = 0; nf < 4; nf++)
#pragma unroll
            for (int r = 0; r < 4; r++) acc[mf][nf][r] = 0.f;

    for (int it = 0; it < 16; it++) {
        const int st = it % 3;
        if (it + 1 < 16) CP_WAIT1(); else CP_WAIT0();
        __syncthreads();
        if (it + 2 < 16) G3_ISSUE((it + 2) * 32, (it + 2) % 3);

        const uint32_t abuf = afrag + st * ASTG;
        const uint32_t bbuf = bfrag + st * BSTG;

        if (MODE == 0) {
#pragma unroll
            for (int kc = 0; kc < 2; kc++) {
                uint32_t af[4][4];
#pragma unroll
                for (int mf = 0; mf < 4; mf++)
                    ldsm4(af[mf], abuf + (uint32_t)((wm * 64 + mf * 16) * 80 + kc * 32));
#pragma unroll
                for (int nf = 0; nf < 2; nf++) {
                    uint32_t kb[4];
                    ldsm4t(kb, bbuf + (uint32_t)(kc * 4352 + wn * 64 + nf * 32));
#pragma unroll
                    for (int mf = 0; mf < 4; mf++) {
                        mma_bf16(acc[mf][nf * 2], af[mf], kb[0], kb[1]);
                        mma_bf16(acc[mf][nf * 2 + 1], af[mf], kb[2], kb[3]);
                    }
                }
            }
        } else {
            uint32_t vb[4][4];
#pragma unroll
            for (int j = 0; j < 4; j++)
                ldsm4(vb[j], bbuf + (uint32_t)((wn * 32 + j * 8) * 80));
#pragma unroll
            for (int kc = 0; kc < 2; kc++) {
                uint32_t af[4][4];
#pragma unroll
                for (int mf = 0; mf < 4; mf++)
                    ldsm4(af[mf], abuf + (uint32_t)((wm * 64 + mf * 16) * 80 + kc * 32));
#pragma unroll
                for (int j = 0; j < 4; j++)
#pragma unroll
                    for (int mf = 0; mf < 4; mf++)
                        mma_bf16(acc[mf][j], af[mf], vb[j][2 * kc], vb[j][2 * kc + 1]);
            }
        }
    }

    // epilogue
#pragma unroll
    for (int mf = 0; mf < 4; mf++) {
        int m = m0 + wm * 64 + mf * 16 + g;
        float bi0 = bias[m], bi1 = bias[m + 8];
#pragma unroll
        for (int nf = 0; nf < 4; nf++) {
            int n = n0 + wn * 32 + nf * 8 + tg * 2;
            float v0 = acc[mf][nf][0] + bi0, v1 = acc[mf][nf][1] + bi0;
            float v2 = acc[mf][nf][2] + bi1, v3 = acc[mf][nf][3] + bi1;
            if (MODE == 0) {
                *(uint32_t*)&Ch[(size_t)m * ldc + n] = packb(v0, v1);
                *(uint32_t*)&Ch[(size_t)(m + 8) * ldc + n] = packb(v2, v3);
            } else {
                float2 r0 = *(const float2*)&resid[(size_t)m * ldc + n];
                float2 r1 = *(const float2*)&resid[(size_t)(m + 8) * ldc + n];
                *(float2*)&Cf[(size_t)m * ldc + n] = make_float2(v0 + r0.x, v1 + r0.y);
                *(float2*)&Cf[(size_t)(m + 8) * ldc + n] = make_float2(v2 + r1.x, v3 + r1.y);
            }
        }
    }
}

// ---------------- fused flash attention (static-max, 8 warps x 16 rows) -------
// 256 threads, q tile 128, KV tile 64, 3-stage cp.async. One A-set per warp ->
// low registers -> 2 CTAs/SM (16 warps/SM) for latency hiding.
#define KSTG 9216    // 64*72*2 per stage (same for V)
#define NKV (NTOK / 64)

__global__ void __launch_bounds__(256, 2)
flash_attn(const __nv_bfloat16* __restrict__ qkv, __nv_bfloat16* __restrict__ aoT) {
    extern __shared__ __align__(16) char fsm[];
    const uint32_t ksmb = (uint32_t)__cvta_generic_to_shared(fsm);
    const uint32_t vsmb = ksmb + 3 * KSTG;

    const int tid = threadIdx.x;
    const int w = tid >> 5, lane = tid & 31;
    const int g = lane >> 2, tg = lane & 3;

    const int b = blockIdx.z, h = blockIdx.y;
    const size_t CN = (size_t)CCH * NTOK;
    const __nv_bfloat16* qg = qkv + (size_t)b * 3 * CN + (size_t)(h * HD) * NTOK;
    const __nv_bfloat16* kg = qg + CN;
    const __nv_bfloat16* vg = qg + 2 * CN;

    const int nq0 = blockIdx.x * 128 + w * 16;   // this warp's 16 q rows

    const uint32_t lb1 = (g == 0) ? 0x3F803F80u : 0u;  // ones B-frag for l

    // cp.async loader: 2 K + 2 V 16B ops per thread per tile (256 threads)
    int ld_d[2], ld_m[2];
    uint32_t kdst[2], vdst[2];
#pragma unroll
    for (int i = 0; i < 2; i++) {
        int e = tid + i * 256;
        ld_d[i] = e >> 3; ld_m[i] = (e & 7) * 8;
        kdst[i] = ksmb + (uint32_t)((ld_d[i] * 72 + ld_m[i]) * 2);
        vdst[i] = vsmb + (uint32_t)((ld_d[i] * 72 + ld_m[i]) * 2);
    }
#define FA_ISSUE(mt, st)                                                       \
    do {                                                                       \
        _Pragma("unroll")                                                      \
        for (int i = 0; i < 2; i++) {                                          \
            CP_ASYNC16(kdst[i] + (st) * KSTG,                                  \
                       kg + (size_t)ld_d[i] * NTOK + (mt) + ld_m[i]);          \
            CP_ASYNC16(vdst[i] + (st) * KSTG,                                  \
                       vg + (size_t)ld_d[i] * NTOK + (mt) + ld_m[i]);          \
        }                                                                      \
        CP_COMMIT();                                                           \
    } while (0)

    FA_ISSUE(0, 0);
    FA_ISSUE(64, 1);

    // Q fragments (scale * log2e folded in): one 16-row A-set
    const float qs = 0.125f * LOG2E;
    uint32_t qa[4][4];
#pragma unroll
    for (int kc = 0; kc < 4; kc++) {
        int d0 = kc * 16 + 2 * tg;
#pragma unroll
        for (int rr = 0; rr < 2; rr++) {
            int q = nq0 + g + rr * 8;
            float lo0 = __bfloat162float(qg[(size_t)d0 * NTOK + q]) * qs;
            float hi0 = __bfloat162float(qg[(size_t)(d0 + 1) * NTOK + q]) * qs;
            float lo8 = __bfloat162float(qg[(size_t)(d0 + 8) * NTOK + q]) * qs;
            float hi8 = __bfloat162float(qg[(size_t)(d0 + 9) * NTOK + q]) * qs;
            qa[kc][rr] = packb(lo0, hi0);
            qa[kc][rr + 2] = packb(lo8, hi8);
        }
    }

    float o[8][4];
    float o_l[4];
#pragma unroll
    for (int i = 0; i < 8; i++)
#pragma unroll
        for (int j = 0; j < 4; j++) o[i][j] = 0.f;
#pragma unroll
    for (int j = 0; j < 4; j++) o_l[j] = 0.f;

    const int mat = lane >> 3, r = lane & 7;
    const uint32_t kfrag = ksmb + (uint32_t)(((mat & 1) * 8 + r) * 144 + (mat >> 1) * 16);
    const uint32_t vfrag = vsmb + (uint32_t)(r * 144 + mat * 16);

    for (int kt = 0; kt < NKV; kt++) {
        const int st = kt % 3;
        if (kt + 1 < NKV) CP_WAIT1(); else CP_WAIT0();
        __syncthreads();
        if (kt + 2 < NKV) FA_ISSUE((kt + 2) * 64, (kt + 2) % 3);

        const uint32_t kst = kfrag + st * KSTG;
        const uint32_t vst = vfrag + st * KSTG;

        // ---- S = Q^T K + SOFF ----
        float c[8][4];
#pragma unroll
        for (int nt = 0; nt < 8; nt++)
            c[nt][0] = c[nt][1] = c[nt][2] = c[nt][3] = SOFF;
#pragma unroll
        for (int p = 0; p < 4; p++)
#pragma unroll
            for (int kc = 0; kc < 4; kc++) {
                uint32_t kb[4];
                ldsm4t(kb, kst + (uint32_t)(kc * 2304 + p * 32));
                mma_bf16(c[2 * p], qa[kc], kb[0], kb[1]);
                mma_bf16(c[2 * p + 1], qa[kc], kb[2], kb[3]);
            }

        // ---- P = exp2(c) packed straight into A-fragments ----
        uint32_t pa[4][4];
        {
            uint32_t pe0[8], pe1[8];
#pragma unroll
            for (int nt = 0; nt < 8; nt++) {
                pe0[nt] = ex2b(c[nt][0], c[nt][1]);
                pe1[nt] = ex2b(c[nt][2], c[nt][3]);
            }
#pragma unroll
            for (int mc = 0; mc < 4; mc++) {
                pa[mc][0] = pe0[2 * mc];
                pa[mc][1] = pe1[2 * mc];
                pa[mc][2] = pe0[2 * mc + 1];
                pa[mc][3] = pe1[2 * mc + 1];
            }
        }

        // ---- l += P @ ones ----
#pragma unroll
        for (int mc = 0; mc < 4; mc++)
            mma_bf16(o_l, pa[mc], lb1, lb1);

        // ---- O += P @ V^T ----
#pragma unroll
        for (int dt = 0; dt < 8; dt++)
#pragma unroll
            for (int mcp = 0; mcp < 2; mcp++) {
                uint32_t vb[4];
                ldsm4(vb, vst + (uint32_t)(dt * 1152 + mcp * 64));
                mma_bf16(o[dt], pa[2 * mcp], vb[0], vb[1]);
                mma_bf16(o[dt], pa[2 * mcp + 1], vb[2], vb[3]);
            }
    }

    // ---- epilogue ----
    __nv_bfloat16* outp = aoT + (size_t)b * CN + (size_t)(h * HD);
    float l0 = __shfl_sync(0xffffffffu, o_l[0], lane & 28);
    float l1 = __shfl_sync(0xffffffffu, o_l[2], lane & 28);
    float inv0 = 1.f / l0, inv1 = 1.f / l1;
#pragma unroll
    for (int dt = 0; dt < 8; dt++) {
        *(uint32_t*)&outp[(size_t)(nq0 + g) * CCH + dt * 8 + tg * 2] =
            packb(o[dt][0] * inv0, o[dt][1] * inv0);
        *(uint32_t*)&outp[(size_t)(nq0 + g + 8) * CCH + dt * 8 + tg * 2] =
            packb(o[dt][2] * inv1, o[dt][3] * inv1);
    }
}

// ---------------- launch ------------------------------------------------------
extern "C" void kernel_launch(void* const* d_in, const int* in_sizes, int n_in,
                              void* d_out, int out_size) {
    const float* x      = (const float*)d_in[0];
    const float* norm_w = (const float*)d_in[1];
    const float* norm_b = (const float*)d_in[2];
    const float* qkv_w  = (const float*)d_in[3];
    const float* qkv_b  = (const float*)d_in[4];
    const float* proj_w = (const float*)d_in[5];
    const float* proj_b = (const float*)d_in[6];
    float* out = (float*)d_out;

    __nv_bfloat16 *hn, *qkv, *aoT, *qkvwb, *projwb;
    cudaGetSymbolAddress((void**)&hn,     g_hn);
    cudaGetSymbolAddress((void**)&qkv,    g_qkv);
    cudaGetSymbolAddress((void**)&aoT,    g_aoT);
    cudaGetSymbolAddress((void**)&qkvwb,  g_qkvwb);
    cudaGetSymbolAddress((void**)&projwb, g_projwb);

    const size_t CN = (size_t)CCH * NTOK;

    const int SM_G0 = 3 * (ASTG + BSTG0);  // 56832
    const int SM_G1 = 3 * (ASTG + BSTG1);  // 61440
    const int SM_FA = 6 * KSTG;            // 55296
    static int attr_done = 0;
    if (!attr_done) {
        cudaFuncSetAttribute(gemm3<0>, cudaFuncAttributeMaxDynamicSharedMemorySize, SM_G0);
        cudaFuncSetAttribute(gemm3<1>, cudaFuncAttributeMaxDynamicSharedMemorySize, SM_G1);
        cudaFuncSetAttribute(flash_attn, cudaFuncAttributeMaxDynamicSharedMemorySize, SM_FA);
        attr_done = 1;
    }

    // 0) weight fp32 -> bf16
    cvt_w<<<(3 * CCH * CCH + CCH * CCH) / 4 / 256, 256>>>(qkv_w, proj_w);

    // 1) GroupNorm (fused, writes bf16 hn)
    gn_fused<<<BATCH * GROUPS, 512>>>(x, norm_w, norm_b);

    // 2) QKV GEMM: bf16 W [1536,512] x hn [512,4096] -> bf16 qkv
    gemm3<0><<<dim3(NTOK / 128, (3 * CCH) / 128, BATCH), 256, SM_G0>>>(
        qkvwb, hn, qkv, CCH, NTOK, NTOK,
        CN, 3 * CN, qkv_b, nullptr, 0);

    // 3) fused attention (static-max, 8 warps x 16 rows, 2 CTAs/SM)
    flash_attn<<<dim3(NTOK / 128, NH, BATCH), 256, SM_FA>>>(qkv, aoT);

    // 4) proj + bias + residual -> fp32 out
    gemm3<1><<<dim3(NTOK / 128, CCH / 128, BATCH), 256, SM_G1>>>(
        projwb, aoT, out, CCH, CCH, NTOK,
        CN, CN, proj_b, x, CN);
}

// round 15
// speedup vs baseline: 1.0156x; 1.0156x over previous
#include <cuda_runtime.h>
#include <cuda_bf16.h>
#include <math.h>
#include <stdint.h>

#define BATCH 2
#define CCH 512
#define NH 8
#define HD 64
#define GROUPS 32
#define NTOK 4096
#define EPS 1e-5f
#define LOG2E 1.44269504f
#define SOFF -8.0f   // static softmax offset (log2 units); logits |c|<~4, safe

// ---------------- scratch (static device globals; no allocation) -------------
__device__ __nv_bfloat16 g_hn[(size_t)BATCH * CCH * NTOK];          // 8 MB
__device__ __nv_bfloat16 g_qkv[(size_t)BATCH * 3 * CCH * NTOK];     // 25 MB
__device__ __nv_bfloat16 g_aoT[(size_t)BATCH * NTOK * CCH];         // 8 MB [b][n][c]
__device__ __nv_bfloat16 g_qkvwb[3 * CCH * CCH];                    // 1.5 MB
__device__ __nv_bfloat16 g_projwb[CCH * CCH];                       // 0.5 MB

// ---------------- helpers -----------------------------------------------------
__device__ __forceinline__ uint32_t packb(float lo, float hi) {
    __nv_bfloat162 t = __floats2bfloat162_rn(lo, hi);
    return *(uint32_t*)&t;
}
__device__ __forceinline__ uint32_t ex2b(float lo, float hi) {
    __nv_bfloat162 t = __floats2bfloat162_rn(lo, hi);
    uint32_t u = *(uint32_t*)&t, y;
    asm("ex2.approx.ftz.bf16x2 %0, %1;" : "=r"(y) : "r"(u));
    return y;
}
__device__ __forceinline__ void mma_bf16(float c[4], const uint32_t a[4],
                                         uint32_t b0, uint32_t b1) {
    asm volatile(
        "mma.sync.aligned.m16n8k16.row.col.f32.bf16.bf16.f32 "
        "{%0,%1,%2,%3}, {%4,%5,%6,%7}, {%8,%9}, {%0,%1,%2,%3};\n"
        : "+f"(c[0]), "+f"(c[1]), "+f"(c[2]), "+f"(c[3])
        : "r"(a[0]), "r"(a[1]), "r"(a[2]), "r"(a[3]), "r"(b0), "r"(b1));
}
__device__ __forceinline__ void ldsm4t(uint32_t r[4], uint32_t addr) {
    asm volatile(
        "ldmatrix.sync.aligned.m8n8.x4.trans.shared.b16 {%0,%1,%2,%3}, [%4];"
        : "=r"(r[0]), "=r"(r[1]), "=r"(r[2]), "=r"(r[3]) : "r"(addr));
}
__device__ __forceinline__ void ldsm4(uint32_t r[4], uint32_t addr) {
    asm volatile(
        "ldmatrix.sync.aligned.m8n8.x4.shared.b16 {%0,%1,%2,%3}, [%4];"
        : "=r"(r[0]), "=r"(r[1]), "=r"(r[2]), "=r"(r[3]) : "r"(addr));
}
#define CP_ASYNC16(dst, src) \
    asm volatile("cp.async.cg.shared.global [%0], [%1], 16;" :: "r"(dst), "l"(src))
#define CP_COMMIT() asm volatile("cp.async.commit_group;")
#define CP_WAIT0() asm volatile("cp.async.wait_group 0;")
#define CP_WAIT1() asm volatile("cp.async.wait_group 1;")

// ---------------- weight conversion fp32 -> bf16 ------------------------------
__global__ void cvt_w(const float* __restrict__ qkv_w, const float* __restrict__ proj_w) {
    const int NQ = 3 * CCH * CCH / 4;
    int i = blockIdx.x * 256 + threadIdx.x;
    if (i < NQ) {
        float4 v = ((const float4*)qkv_w)[i];
        uint2 o; o.x = packb(v.x, v.y); o.y = packb(v.z, v.w);
        ((uint2*)g_qkvwb)[i] = o;
    } else {
        int j = i - NQ;
        float4 v = ((const float4*)proj_w)[j];
        uint2 o; o.x = packb(v.x, v.y); o.y = packb(v.z, v.w);
        ((uint2*)g_projwb)[j] = o;
    }
}

// ---------------- GroupNorm: fused single kernel ------------------------------
__global__ void __launch_bounds__(512)
gn_fused(const float* __restrict__ x,
         const float* __restrict__ w,
         const float* __restrict__ b) {
    const int bg = blockIdx.x;
    const int g = bg % GROUPS;
    const int tid = threadIdx.x;
    const float4* xp = (const float4*)x + (size_t)bg * 16384;
    uint2* hp = (uint2*)(g_hn + (size_t)bg * 65536);

    float s = 0.f, s2 = 0.f;
#pragma unroll 8
    for (int i = tid; i < 16384; i += 512) {
        float4 v = xp[i];
        s += v.x + v.y + v.z + v.w;
        s2 += v.x * v.x + v.y * v.y + v.z * v.z + v.w * v.w;
    }
    __shared__ float sh[512], sh2[512];
    sh[tid] = s; sh2[tid] = s2;
    __syncthreads();
    for (int o = 256; o > 0; o >>= 1) {
        if (tid < o) { sh[tid] += sh[tid + o]; sh2[tid] += sh2[tid + o]; }
        __syncthreads();
    }
    float mean = sh[0] / 65536.f;
    float var  = sh2[0] / 65536.f - mean * mean;
    float inv  = rsqrtf(var + EPS);

#pragma unroll 8
    for (int i = tid; i < 16384; i += 512) {
        int ch = g * 16 + (i >> 10);
        float sc = inv * w[ch];
        float off = b[ch] - mean * sc;
        float4 v = xp[i];
        uint2 o;
        o.x = packb(v.x * sc + off, v.y * sc + off);
        o.y = packb(v.z * sc + off, v.w * sc + off);
        hp[i] = o;
    }
}

// ---------------- bf16 GEMM (best measured): cp.async, BK=32, 3-stage ---------
#define ASTG 10240   // 128*40*2
#define BSTG0 8704   // 32*136*2
#define BSTG1 10240  // 128*40*2
template <int MODE>
__global__ void __launch_bounds__(256, 2)
gemm3(const __nv_bfloat16* __restrict__ A, const __nv_bfloat16* __restrict__ B,
      void* __restrict__ Cv, int lda, int ldb, int ldc,
      size_t sB, size_t sC,
      const float* __restrict__ bias,
      const float* __restrict__ resid, size_t sR) {
    constexpr int BSTG = (MODE == 0) ? BSTG0 : BSTG1;
    extern __shared__ __align__(16) char gsm[];
    const uint32_t asmb = (uint32_t)__cvta_generic_to_shared(gsm);
    const uint32_t bsmb = asmb + 3 * ASTG;

    const int tid = threadIdx.x;
    const int w = tid >> 5, lane = tid & 31;
    const int g = lane >> 2, tg = lane & 3;
    const int wm = w >> 2, wn = w & 3;
    const int m0 = blockIdx.y * 128;
    const int n0 = blockIdx.x * 128;

    B += (size_t)blockIdx.z * sB;
    float* Cf = (float*)Cv + (MODE == 1 ? (size_t)blockIdx.z * sC : 0);
    __nv_bfloat16* Ch = (__nv_bfloat16*)Cv + (MODE == 0 ? (size_t)blockIdx.z * sC : 0);
    if (MODE == 1 && resid) resid += (size_t)blockIdx.z * sR;

    int ar[2], ac[2], br[2], bc[2];
    uint32_t adst[2], bdst[2];
#pragma unroll
    for (int i = 0; i < 2; i++) {
        int e = tid + i * 256;
        ar[i] = e >> 2; ac[i] = (e & 3) * 8;
        adst[i] = asmb + (uint32_t)((ar[i] * 40 + ac[i]) * 2);
        if (MODE == 0) {
            br[i] = e >> 4; bc[i] = (e & 15) * 8;
            bdst[i] = bsmb + (uint32_t)((br[i] * 136 + bc[i]) * 2);
        } else {
            br[i] = e >> 2; bc[i] = (e & 3) * 8;
            bdst[i] = bsmb + (uint32_t)((br[i] * 40 + bc[i]) * 2);
        }
    }

#define G3_ISSUE(kk, st)                                                        \
    do {                                                                        \
        _Pragma("unroll")                                                       \
        for (int i = 0; i < 2; i++) {                                           \
            CP_ASYNC16(adst[i] + (st) * ASTG,                                   \
                       &A[(size_t)(m0 + ar[i]) * lda + (kk) + ac[i]]);          \
            if (MODE == 0)                                                      \
                CP_ASYNC16(bdst[i] + (st) * BSTG,                               \
                           &B[(size_t)((kk) + br[i]) * ldb + n0 + bc[i]]);      \
            else                                                                \
                CP_ASYNC16(bdst[i] + (st) * BSTG,                               \
                           &B[(size_t)(n0 + br[i]) * ldb + (kk) + bc[i]]);      \
        }                                                                       \
        CP_COMMIT();                                                            \
    } while (0)

    G3_ISSUE(0, 0);
    G3_ISSUE(32, 1);

    const uint32_t afrag = asmb + (uint32_t)((lane & 15) * 80 + (lane >> 4) * 16);
    uint32_t bfrag;
    if (MODE == 0)
        bfrag = bsmb + (uint32_t)((((lane >> 3 & 1) * 8) + (lane & 7)) * 272 + (lane >> 4) * 16);
    else
        bfrag = bsmb + (uint32_t)((lane & 7) * 80 + (lane >> 3) * 16);

    float acc[4][4][4];
#pragma unroll
    for (int mf = 0; mf < 4; mf++)
#pragma unroll
        for (int nf = 0; nf < 4; nf++)
#pragma unroll
            for (int r = 0; r < 4; r++) acc[mf][nf][r] = 0.f;

    for (int it = 0; it < 16; it++) {
        const int st = it % 3;
        if (it + 1 < 16) CP_WAIT1(); else CP_WAIT0();
        __syncthreads();
        if (it + 2 < 16) G3_ISSUE((it + 2) * 32, (it + 2) % 3);

        const uint32_t abuf = afrag + st * ASTG;
        const uint32_t bbuf = bfrag + st * BSTG;

        if (MODE == 0) {
#pragma unroll
            for (int kc = 0; kc < 2; kc++) {
                uint32_t af[4][4];
#pragma unroll
                for (int mf = 0; mf < 4; mf++)
                    ldsm4(af[mf], abuf + (uint32_t)((wm * 64 + mf * 16) * 80 + kc * 32));
#pragma unroll
                for (int nf = 0; nf < 2; nf++) {
                    uint32_t kb[4];
                    ldsm4t(kb, bbuf + (uint32_t)(kc * 4352 + wn * 64 + nf * 32));
#pragma unroll
                    for (int mf = 0; mf < 4; mf++) {
                        mma_bf16(acc[mf][nf * 2], af[mf], kb[0], kb[1]);
                        mma_bf16(acc[mf][nf * 2 + 1], af[mf], kb[2], kb[3]);
                    }
                }
            }
        } else {
            uint32_t vb[4][4];
#pragma unroll
            for (int j = 0; j < 4; j++)
                ldsm4(vb[j], bbuf + (uint32_t)((wn * 32 + j * 8) * 80));
#pragma unroll
            for (int kc = 0; kc < 2; kc++) {
                uint32_t af[4][4];
#pragma unroll
                for (int mf = 0; mf < 4; mf++)
                    ldsm4(af[mf], abuf + (uint32_t)((wm * 64 + mf * 16) * 80 + kc * 32));
#pragma unroll
                for (int j = 0; j < 4; j++)
#pragma unroll
                    for (int mf = 0; mf < 4; mf++)
                        mma_bf16(acc[mf][j], af[mf], vb[j][2 * kc], vb[j][2 * kc + 1]);
            }
        }
    }

    // epilogue
#pragma unroll
    for (int mf = 0; mf < 4; mf++) {
        int m = m0 + wm * 64 + mf * 16 + g;
        float bi0 = bias[m], bi1 = bias[m + 8];
#pragma unroll
        for (int nf = 0; nf < 4; nf++) {
            int n = n0 + wn * 32 + nf * 8 + tg * 2;
            float v0 = acc[mf][nf][0] + bi0, v1 = acc[mf][nf][1] + bi0;
            float v2 = acc[mf][nf][2] + bi1, v3 = acc[mf][nf][3] + bi1;
            if (MODE == 0) {
                *(uint32_t*)&Ch[(size_t)m * ldc + n] = packb(v0, v1);
                *(uint32_t*)&Ch[(size_t)(m + 8) * ldc + n] = packb(v2, v3);
            } else {
                float2 r0 = *(const float2*)&resid[(size_t)m * ldc + n];
                float2 r1 = *(const float2*)&resid[(size_t)(m + 8) * ldc + n];
                *(float2*)&Cf[(size_t)m * ldc + n] = make_float2(v0 + r0.x, v1 + r0.y);
                *(float2*)&Cf[(size_t)(m + 8) * ldc + n] = make_float2(v2 + r1.x, v3 + r1.y);
            }
        }
    }
}

// ---------------- fused flash attention (static-max, R12 shape, 3 CTAs/SM) ----
// 4 warps x 32 q-rows, 128 threads, KV tile 64, 3-stage cp.async.
// __launch_bounds__(128,3): cap regs ~170 -> 3 CTAs/SM (12 warps) for latency
// hiding + better wave tail (512 CTAs / 444 slots).
#define KSTG 9216    // 64*72*2 per stage (same for V)
#define NKV (NTOK / 64)

__global__ void __launch_bounds__(128, 3)
flash_attn(const __nv_bfloat16* __restrict__ qkv, __nv_bfloat16* __restrict__ aoT) {
    extern __shared__ __align__(16) char fsm[];
    const uint32_t ksmb = (uint32_t)__cvta_generic_to_shared(fsm);
    const uint32_t vsmb = ksmb + 3 * KSTG;

    const int tid = threadIdx.x;
    const int w = tid >> 5, lane = tid & 31;
    const int g = lane >> 2, tg = lane & 3;

    const int b = blockIdx.z, h = blockIdx.y;
    const size_t CN = (size_t)CCH * NTOK;
    const __nv_bfloat16* qg = qkv + (size_t)b * 3 * CN + (size_t)(h * HD) * NTOK;
    const __nv_bfloat16* kg = qg + CN;
    const __nv_bfloat16* vg = qg + 2 * CN;

    const int nq0 = blockIdx.x * 128 + w * 32;

    const uint32_t lb1 = (g == 0) ? 0x3F803F80u : 0u;  // ones B-frag for l

    int ld_d[4], ld_m[4];
    uint32_t kdst[4], vdst[4];
#pragma unroll
    for (int i = 0; i < 4; i++) {
        int e = tid + i * 128;
        ld_d[i] = e >> 3; ld_m[i] = (e & 7) * 8;
        kdst[i] = ksmb + (uint32_t)((ld_d[i] * 72 + ld_m[i]) * 2);
        vdst[i] = vsmb + (uint32_t)((ld_d[i] * 72 + ld_m[i]) * 2);
    }
#define FA_ISSUE(mt, st)                                                       \
    do {                                                                       \
        _Pragma("unroll")                                                      \
        for (int i = 0; i < 4; i++) {                                          \
            CP_ASYNC16(kdst[i] + (st) * KSTG,                                  \
                       kg + (size_t)ld_d[i] * NTOK + (mt) + ld_m[i]);          \
            CP_ASYNC16(vdst[i] + (st) * KSTG,                                  \
                       vg + (size_t)ld_d[i] * NTOK + (mt) + ld_m[i]);          \
        }                                                                      \
        CP_COMMIT();                                                           \
    } while (0)

    FA_ISSUE(0, 0);
    FA_ISSUE(64, 1);

    const float qs = 0.125f * LOG2E;
    uint32_t qa[2][4][4];
#pragma unroll
    for (int s = 0; s < 2; s++)
#pragma unroll
        for (int kc = 0; kc < 4; kc++) {
            int d0 = kc * 16 + 2 * tg;
#pragma unroll
            for (int rr = 0; rr < 2; rr++) {
                int q = nq0 + s * 16 + g + rr * 8;
                float lo0 = __bfloat162float(qg[(size_t)d0 * NTOK + q]) * qs;
                float hi0 = __bfloat162float(qg[(size_t)(d0 + 1) * NTOK + q]) * qs;
                float lo8 = __bfloat162float(qg[(size_t)(d0 + 8) * NTOK + q]) * qs;
                float hi8 = __bfloat162float(qg[(size_t)(d0 + 9) * NTOK + q]) * qs;
                qa[s][kc][rr] = packb(lo0, hi0);
                qa[s][kc][rr + 2] = packb(lo8, hi8);
            }
        }

    float o[2][8][4];
    float o_l[2][4];
#pragma unroll
    for (int s = 0; s < 2; s++) {
#pragma unroll
        for (int i = 0; i < 8; i++)
#pragma unroll
            for (int j = 0; j < 4; j++) o[s][i][j] = 0.f;
#pragma unroll
        for (int j = 0; j < 4; j++) o_l[s][j] = 0.f;
    }

    const int mat = lane >> 3, r = lane & 7;
    const uint32_t kfrag = ksmb + (uint32_t)(((mat & 1) * 8 + r) * 144 + (mat >> 1) * 16);
    const uint32_t vfrag = vsmb + (uint32_t)(r * 144 + mat * 16);

    for (int kt = 0; kt < NKV; kt++) {
        const int st = kt % 3;
        if (kt + 1 < NKV) CP_WAIT1(); else CP_WAIT0();
        __syncthreads();
        if (kt + 2 < NKV) FA_ISSUE((kt + 2) * 64, (kt + 2) % 3);

        const uint32_t kst = kfrag + st * KSTG;
        const uint32_t vst = vfrag + st * KSTG;

        // ---- S = Q^T K + SOFF ----
        float c[2][8][4];
#pragma unroll
        for (int s = 0; s < 2; s++)
#pragma unroll
            for (int nt = 0; nt < 8; nt++)
                c[s][nt][0] = c[s][nt][1] = c[s][nt][2] = c[s][nt][3] = SOFF;
#pragma unroll
        for (int p = 0; p < 4; p++)
#pragma unroll
            for (int kc = 0; kc < 4; kc++) {
                uint32_t kb[4];
                ldsm4t(kb, kst + (uint32_t)(kc * 2304 + p * 32));
                mma_bf16(c[0][2 * p], qa[0][kc], kb[0], kb[1]);
                mma_bf16(c[1][2 * p], qa[1][kc], kb[0], kb[1]);
                mma_bf16(c[0][2 * p + 1], qa[0][kc], kb[2], kb[3]);
                mma_bf16(c[1][2 * p + 1], qa[1][kc], kb[2], kb[3]);
            }

        // ---- P = exp2(c) packed straight into A-fragments ----
        uint32_t pa[2][4][4];
#pragma unroll
        for (int s = 0; s < 2; s++) {
            uint32_t pe0[8], pe1[8];
#pragma unroll
            for (int nt = 0; nt < 8; nt++) {
                pe0[nt] = ex2b(c[s][nt][0], c[s][nt][1]);
                pe1[nt] = ex2b(c[s][nt][2], c[s][nt][3]);
            }
#pragma unroll
            for (int mc = 0; mc < 4; mc++) {
                pa[s][mc][0] = pe0[2 * mc];
                pa[s][mc][1] = pe1[2 * mc];
                pa[s][mc][2] = pe0[2 * mc + 1];
                pa[s][mc][3] = pe1[2 * mc + 1];
            }
        }

        // ---- l += P @ ones ----
#pragma unroll
        for (int mc = 0; mc < 4; mc++) {
            mma_bf16(o_l[0], pa[0][mc], lb1, lb1);
            mma_bf16(o_l[1], pa[1][mc], lb1, lb1);
        }

        // ---- O += P @ V^T ----
#pragma unroll
        for (int dt = 0; dt < 8; dt++)
#pragma unroll
            for (int mcp = 0; mcp < 2; mcp++) {
                uint32_t vb[4];
                ldsm4(vb, vst + (uint32_t)(dt * 1152 + mcp * 64));
                mma_bf16(o[0][dt], pa[0][2 * mcp], vb[0], vb[1]);
                mma_bf16(o[1][dt], pa[1][2 * mcp], vb[0], vb[1]);
                mma_bf16(o[0][dt], pa[0][2 * mcp + 1], vb[2], vb[3]);
                mma_bf16(o[1][dt], pa[1][2 * mcp + 1], vb[2], vb[3]);
            }
    }

    // ---- epilogue ----
    __nv_bfloat16* outp = aoT + (size_t)b * CN + (size_t)(h * HD);
#pragma unroll
    for (int s = 0; s < 2; s++) {
        float l0 = __shfl_sync(0xffffffffu, o_l[s][0], lane & 28);
        float l1 = __shfl_sync(0xffffffffu, o_l[s][2], lane & 28);
        float inv0 = 1.f / l0, inv1 = 1.f / l1;
        int q0 = nq0 + s * 16;
#pragma unroll
        for (int dt = 0; dt < 8; dt++) {
            *(uint32_t*)&outp[(size_t)(q0 + g) * CCH + dt * 8 + tg * 2] =
                packb(o[s][dt][0] * inv0, o[s][dt][1] * inv0);
            *(uint32_t*)&outp[(size_t)(q0 + g + 8) * CCH + dt * 8 + tg * 2] =
                packb(o[s][dt][2] * inv1, o[s][dt][3] * inv1);
        }
    }
}

// ---------------- launch ------------------------------------------------------
extern "C" void kernel_launch(void* const* d_in, const int* in_sizes, int n_in,
                              void* d_out, int out_size) {
    const float* x      = (const float*)d_in[0];
    const float* norm_w = (const float*)d_in[1];
    const float* norm_b = (const float*)d_in[2];
    const float* qkv_w  = (const float*)d_in[3];
    const float* qkv_b  = (const float*)d_in[4];
    const float* proj_w = (const float*)d_in[5];
    const float* proj_b = (const float*)d_in[6];
    float* out = (float*)d_out;

    __nv_bfloat16 *hn, *qkv, *aoT, *qkvwb, *projwb;
    cudaGetSymbolAddress((void**)&hn,     g_hn);
    cudaGetSymbolAddress((void**)&qkv,    g_qkv);
    cudaGetSymbolAddress((void**)&aoT,    g_aoT);
    cudaGetSymbolAddress((void**)&qkvwb,  g_qkvwb);
    cudaGetSymbolAddress((void**)&projwb, g_projwb);

    const size_t CN = (size_t)CCH * NTOK;

    const int SM_G0 = 3 * (ASTG + BSTG0);  // 56832
    const int SM_G1 = 3 * (ASTG + BSTG1);  // 61440
    const int SM_FA = 6 * KSTG;            // 55296
    static int attr_done = 0;
    if (!attr_done) {
        cudaFuncSetAttribute(gemm3<0>, cudaFuncAttributeMaxDynamicSharedMemorySize, SM_G0);
        cudaFuncSetAttribute(gemm3<1>, cudaFuncAttributeMaxDynamicSharedMemorySize, SM_G1);
        cudaFuncSetAttribute(flash_attn, cudaFuncAttributeMaxDynamicSharedMemorySize, SM_FA);
        attr_done = 1;
    }

    // 0) weight fp32 -> bf16
    cvt_w<<<(3 * CCH * CCH + CCH * CCH) / 4 / 256, 256>>>(qkv_w, proj_w);

    // 1) GroupNorm (fused, writes bf16 hn)
    gn_fused<<<BATCH * GROUPS, 512>>>(x, norm_w, norm_b);

    // 2) QKV GEMM: bf16 W [1536,512] x hn [512,4096] -> bf16 qkv
    gemm3<0><<<dim3(NTOK / 128, (3 * CCH) / 128, BATCH), 256, SM_G0>>>(
        qkvwb, hn, qkv, CCH, NTOK, NTOK,
        CN, 3 * CN, qkv_b, nullptr, 0);

    // 3) fused attention (static-max, 4 warps x 32 rows, 3 CTAs/SM)
    flash_attn<<<dim3(NTOK / 128, NH, BATCH), 128, SM_FA>>>(qkv, aoT);

    // 4) proj + bias + residual -> fp32 out
    gemm3<1><<<dim3(NTOK / 128, CCH / 128, BATCH), 256, SM_G1>>>(
        projwb, aoT, out, CCH, CCH, NTOK,
        CN, CN, proj_b, x, CN);
}

// round 16
// speedup vs baseline: 1.0766x; 1.0601x over previous
#include <cuda_runtime.h>
#include <cuda_bf16.h>
#include <math.h>
#include <stdint.h>

#define BATCH 2
#define CCH 512
#define NH 8
#define HD 64
#define GROUPS 32
#define NTOK 4096
#define EPS 1e-5f
#define LOG2E 1.44269504f
#define SOFF -8.0f   // static softmax offset (log2 units); logits |c|<~4, safe

// ---------------- scratch (static device globals; no allocation) -------------
__device__ __nv_bfloat16 g_hn[(size_t)BATCH * CCH * NTOK];          // 8 MB
__device__ __nv_bfloat16 g_qkv[(size_t)BATCH * 3 * CCH * NTOK];     // 25 MB
__device__ __nv_bfloat16 g_aoT[(size_t)BATCH * NTOK * CCH];         // 8 MB [b][n][c]
__device__ __nv_bfloat16 g_qkvwb[3 * CCH * CCH];                    // 1.5 MB
__device__ __nv_bfloat16 g_projwb[CCH * CCH];                       // 0.5 MB

// ---------------- helpers -----------------------------------------------------
__device__ __forceinline__ uint32_t packb(float lo, float hi) {
    __nv_bfloat162 t = __floats2bfloat162_rn(lo, hi);
    return *(uint32_t*)&t;
}
__device__ __forceinline__ uint32_t ex2b(float lo, float hi) {
    __nv_bfloat162 t = __floats2bfloat162_rn(lo, hi);
    uint32_t u = *(uint32_t*)&t, y;
    asm("ex2.approx.ftz.bf16x2 %0, %1;" : "=r"(y) : "r"(u));
    return y;
}
__device__ __forceinline__ void mma_bf16(float c[4], const uint32_t a[4],
                                         uint32_t b0, uint32_t b1) {
    asm volatile(
        "mma.sync.aligned.m16n8k16.row.col.f32.bf16.bf16.f32 "
        "{%0,%1,%2,%3}, {%4,%5,%6,%7}, {%8,%9}, {%0,%1,%2,%3};\n"
        : "+f"(c[0]), "+f"(c[1]), "+f"(c[2]), "+f"(c[3])
        : "r"(a[0]), "r"(a[1]), "r"(a[2]), "r"(a[3]), "r"(b0), "r"(b1));
}
__device__ __forceinline__ void ldsm4t(uint32_t r[4], uint32_t addr) {
    asm volatile(
        "ldmatrix.sync.aligned.m8n8.x4.trans.shared.b16 {%0,%1,%2,%3}, [%4];"
        : "=r"(r[0]), "=r"(r[1]), "=r"(r[2]), "=r"(r[3]) : "r"(addr));
}
__device__ __forceinline__ void ldsm4(uint32_t r[4], uint32_t addr) {
    asm volatile(
        "ldmatrix.sync.aligned.m8n8.x4.shared.b16 {%0,%1,%2,%3}, [%4];"
        : "=r"(r[0]), "=r"(r[1]), "=r"(r[2]), "=r"(r[3]) : "r"(addr));
}
#define CP_ASYNC16(dst, src) \
    asm volatile("cp.async.cg.shared.global [%0], [%1], 16;" :: "r"(dst), "l"(src))
#define CP_COMMIT() asm volatile("cp.async.commit_group;")
#define CP_WAIT0() asm volatile("cp.async.wait_group 0;")
#define CP_WAIT1() asm volatile("cp.async.wait_group 1;")

// ---------------- weight conversion fp32 -> bf16 ------------------------------
__global__ void cvt_w(const float* __restrict__ qkv_w, const float* __restrict__ proj_w) {
    const int NQ = 3 * CCH * CCH / 4;
    int i = blockIdx.x * 256 + threadIdx.x;
    if (i < NQ) {
        float4 v = ((const float4*)qkv_w)[i];
        uint2 o; o.x = packb(v.x, v.y); o.y = packb(v.z, v.w);
        ((uint2*)g_qkvwb)[i] = o;
    } else {
        int j = i - NQ;
        float4 v = ((const float4*)proj_w)[j];
        uint2 o; o.x = packb(v.x, v.y); o.y = packb(v.z, v.w);
        ((uint2*)g_projwb)[j] = o;
    }
}

// ---------------- GroupNorm: fused single kernel ------------------------------
__global__ void __launch_bounds__(512)
gn_fused(const float* __restrict__ x,
         const float* __restrict__ w,
         const float* __restrict__ b) {
    const int bg = blockIdx.x;
    const int g = bg % GROUPS;
    const int tid = threadIdx.x;
    const float4* xp = (const float4*)x + (size_t)bg * 16384;
    uint2* hp = (uint2*)(g_hn + (size_t)bg * 65536);

    float s = 0.f, s2 = 0.f;
#pragma unroll 8
    for (int i = tid; i < 16384; i += 512) {
        float4 v = xp[i];
        s += v.x + v.y + v.z + v.w;
        s2 += v.x * v.x + v.y * v.y + v.z * v.z + v.w * v.w;
    }
    __shared__ float sh[512], sh2[512];
    sh[tid] = s; sh2[tid] = s2;
    __syncthreads();
    for (int o = 256; o > 0; o >>= 1) {
        if (tid < o) { sh[tid] += sh[tid + o]; sh2[tid] += sh2[tid + o]; }
        __syncthreads();
    }
    float mean = sh[0] / 65536.f;
    float var  = sh2[0] / 65536.f - mean * mean;
    float inv  = rsqrtf(var + EPS);

#pragma unroll 8
    for (int i = tid; i < 16384; i += 512) {
        int ch = g * 16 + (i >> 10);
        float sc = inv * w[ch];
        float off = b[ch] - mean * sc;
        float4 v = xp[i];
        uint2 o;
        o.x = packb(v.x * sc + off, v.y * sc + off);
        o.y = packb(v.z * sc + off, v.w * sc + off);
        hp[i] = o;
    }
}

// ---------------- bf16 GEMM (best measured): cp.async, BK=32, 3-stage ---------
#define ASTG 10240   // 128*40*2
#define BSTG0 8704   // 32*136*2
#define BSTG1 10240  // 128*40*2
template <int MODE>
__global__ void __launch_bounds__(256, 2)
gemm3(const __nv_bfloat16* __restrict__ A, const __nv_bfloat16* __restrict__ B,
      void* __restrict__ Cv, int lda, int ldb, int ldc,
      size_t sB, size_t sC,
      const float* __restrict__ bias,
      const float* __restrict__ resid, size_t sR) {
    constexpr int BSTG = (MODE == 0) ? BSTG0 : BSTG1;
    extern __shared__ __align__(16) char gsm[];
    const uint32_t asmb = (uint32_t)__cvta_generic_to_shared(gsm);
    const uint32_t bsmb = asmb + 3 * ASTG;

    const int tid = threadIdx.x;
    const int w = tid >> 5, lane = tid & 31;
    const int g = lane >> 2, tg = lane & 3;
    const int wm = w >> 2, wn = w & 3;
    const int m0 = blockIdx.y * 128;
    const int n0 = blockIdx.x * 128;

    B += (size_t)blockIdx.z * sB;
    float* Cf = (float*)Cv + (MODE == 1 ? (size_t)blockIdx.z * sC : 0);
    __nv_bfloat16* Ch = (__nv_bfloat16*)Cv + (MODE == 0 ? (size_t)blockIdx.z * sC : 0);
    if (MODE == 1 && resid) resid += (size_t)blockIdx.z * sR;

    int ar[2], ac[2], br[2], bc[2];
    uint32_t adst[2], bdst[2];
#pragma unroll
    for (int i = 0; i < 2; i++) {
        int e = tid + i * 256;
        ar[i] = e >> 2; ac[i] = (e & 3) * 8;
        adst[i] = asmb + (uint32_t)((ar[i] * 40 + ac[i]) * 2);
        if (MODE == 0) {
            br[i] = e >> 4; bc[i] = (e & 15) * 8;
            bdst[i] = bsmb + (uint32_t)((br[i] * 136 + bc[i]) * 2);
        } else {
            br[i] = e >> 2; bc[i] = (e & 3) * 8;
            bdst[i] = bsmb + (uint32_t)((br[i] * 40 + bc[i]) * 2);
        }
    }

#define G3_ISSUE(kk, st)                                                        \
    do {                                                                        \
        _Pragma("unroll")                                                       \
        for (int i = 0; i < 2; i++) {                                           \
            CP_ASYNC16(adst[i] + (st) * ASTG,                                   \
                       &A[(size_t)(m0 + ar[i]) * lda + (kk) + ac[i]]);          \
            if (MODE == 0)                                                      \
                CP_ASYNC16(bdst[i] + (st) * BSTG,                               \
                           &B[(size_t)((kk) + br[i]) * ldb + n0 + bc[i]]);      \
            else                                                                \
                CP_ASYNC16(bdst[i] + (st) * BSTG,                               \
                           &B[(size_t)(n0 + br[i]) * ldb + (kk) + bc[i]]);      \
        }                                                                       \
        CP_COMMIT();                                                            \
    } while (0)

    G3_ISSUE(0, 0);
    G3_ISSUE(32, 1);

    const uint32_t afrag = asmb + (uint32_t)((lane & 15) * 80 + (lane >> 4) * 16);
    uint32_t bfrag;
    if (MODE == 0)
        bfrag = bsmb + (uint32_t)((((lane >> 3 & 1) * 8) + (lane & 7)) * 272 + (lane >> 4) * 16);
    else
        bfrag = bsmb + (uint32_t)((lane & 7) * 80 + (lane >> 3) * 16);

    float acc[4][4][4];
#pragma unroll
    for (int mf = 0; mf < 4; mf++)
#pragma unroll
        for (int nf = 0; nf < 4; nf++)
#pragma unroll
            for (int r = 0; r < 4; r++) acc[mf][nf][r] = 0.f;

    for (int it = 0; it < 16; it++) {
        const int st = it % 3;
        if (it + 1 < 16) CP_WAIT1(); else CP_WAIT0();
        __syncthreads();
        if (it + 2 < 16) G3_ISSUE((it + 2) * 32, (it + 2) % 3);

        const uint32_t abuf = afrag + st * ASTG;
        const uint32_t bbuf = bfrag + st * BSTG;

        if (MODE == 0) {
#pragma unroll
            for (int kc = 0; kc < 2; kc++) {
                uint32_t af[4][4];
#pragma unroll
                for (int mf = 0; mf < 4; mf++)
                    ldsm4(af[mf], abuf + (uint32_t)((wm * 64 + mf * 16) * 80 + kc * 32));
#pragma unroll
                for (int nf = 0; nf < 2; nf++) {
                    uint32_t kb[4];
                    ldsm4t(kb, bbuf + (uint32_t)(kc * 4352 + wn * 64 + nf * 32));
#pragma unroll
                    for (int mf = 0; mf < 4; mf++) {
                        mma_bf16(acc[mf][nf * 2], af[mf], kb[0], kb[1]);
                        mma_bf16(acc[mf][nf * 2 + 1], af[mf], kb[2], kb[3]);
                    }
                }
            }
        } else {
            uint32_t vb[4][4];
#pragma unroll
            for (int j = 0; j < 4; j++)
                ldsm4(vb[j], bbuf + (uint32_t)((wn * 32 + j * 8) * 80));
#pragma unroll
            for (int kc = 0; kc < 2; kc++) {
                uint32_t af[4][4];
#pragma unroll
                for (int mf = 0; mf < 4; mf++)
                    ldsm4(af[mf], abuf + (uint32_t)((wm * 64 + mf * 16) * 80 + kc * 32));
#pragma unroll
                for (int j = 0; j < 4; j++)
#pragma unroll
                    for (int mf = 0; mf < 4; mf++)
                        mma_bf16(acc[mf][j], af[mf], vb[j][2 * kc], vb[j][2 * kc + 1]);
            }
        }
    }

    // epilogue
#pragma unroll
    for (int mf = 0; mf < 4; mf++) {
        int m = m0 + wm * 64 + mf * 16 + g;
        float bi0 = bias[m], bi1 = bias[m + 8];
#pragma unroll
        for (int nf = 0; nf < 4; nf++) {
            int n = n0 + wn * 32 + nf * 8 + tg * 2;
            float v0 = acc[mf][nf][0] + bi0, v1 = acc[mf][nf][1] + bi0;
            float v2 = acc[mf][nf][2] + bi1, v3 = acc[mf][nf][3] + bi1;
            if (MODE == 0) {
                *(uint32_t*)&Ch[(size_t)m * ldc + n] = packb(v0, v1);
                *(uint32_t*)&Ch[(size_t)(m + 8) * ldc + n] = packb(v2, v3);
            } else {
                float2 r0 = *(const float2*)&resid[(size_t)m * ldc + n];
                float2 r1 = *(const float2*)&resid[(size_t)(m + 8) * ldc + n];
                *(float2*)&Cf[(size_t)m * ldc + n] = make_float2(v0 + r0.x, v1 + r0.y);
                *(float2*)&Cf[(size_t)(m + 8) * ldc + n] = make_float2(v2 + r1.x, v3 + r1.y);
            }
        }
    }
}

// ---------------- fused flash attention (static-max, MUFU/tensor interleave) --
// 4 warps x 32 q-rows, 128 threads, KV tile 64, 3-stage cp.async (R12 shape).
// Tile body: S-MMAs -> ex2(s0) -> l/PV(s0) with ex2(s1) WOVEN between the PV
// MMAs (MUFU overlaps tensor drain) -> l/PV(s1).
#define KSTG 9216    // 64*72*2 per stage (same for V)
#define NKV (NTOK / 64)

__global__ void __launch_bounds__(128)
flash_attn(const __nv_bfloat16* __restrict__ qkv, __nv_bfloat16* __restrict__ aoT) {
    extern __shared__ __align__(16) char fsm[];
    const uint32_t ksmb = (uint32_t)__cvta_generic_to_shared(fsm);
    const uint32_t vsmb = ksmb + 3 * KSTG;

    const int tid = threadIdx.x;
    const int w = tid >> 5, lane = tid & 31;
    const int g = lane >> 2, tg = lane & 3;

    const int b = blockIdx.z, h = blockIdx.y;
    const size_t CN = (size_t)CCH * NTOK;
    const __nv_bfloat16* qg = qkv + (size_t)b * 3 * CN + (size_t)(h * HD) * NTOK;
    const __nv_bfloat16* kg = qg + CN;
    const __nv_bfloat16* vg = qg + 2 * CN;

    const int nq0 = blockIdx.x * 128 + w * 32;

    const uint32_t lb1 = (g == 0) ? 0x3F803F80u : 0u;  // ones B-frag for l

    int ld_d[4], ld_m[4];
    uint32_t kdst[4], vdst[4];
#pragma unroll
    for (int i = 0; i < 4; i++) {
        int e = tid + i * 128;
        ld_d[i] = e >> 3; ld_m[i] = (e & 7) * 8;
        kdst[i] = ksmb + (uint32_t)((ld_d[i] * 72 + ld_m[i]) * 2);
        vdst[i] = vsmb + (uint32_t)((ld_d[i] * 72 + ld_m[i]) * 2);
    }
#define FA_ISSUE(mt, st)                                                       \
    do {                                                                       \
        _Pragma("unroll")                                                      \
        for (int i = 0; i < 4; i++) {                                          \
            CP_ASYNC16(kdst[i] + (st) * KSTG,                                  \
                       kg + (size_t)ld_d[i] * NTOK + (mt) + ld_m[i]);          \
            CP_ASYNC16(vdst[i] + (st) * KSTG,                                  \
                       vg + (size_t)ld_d[i] * NTOK + (mt) + ld_m[i]);          \
        }                                                                      \
        CP_COMMIT();                                                           \
    } while (0)

    FA_ISSUE(0, 0);
    FA_ISSUE(64, 1);

    const float qs = 0.125f * LOG2E;
    uint32_t qa[2][4][4];
#pragma unroll
    for (int s = 0; s < 2; s++)
#pragma unroll
        for (int kc = 0; kc < 4; kc++) {
            int d0 = kc * 16 + 2 * tg;
#pragma unroll
            for (int rr = 0; rr < 2; rr++) {
                int q = nq0 + s * 16 + g + rr * 8;
                float lo0 = __bfloat162float(qg[(size_t)d0 * NTOK + q]) * qs;
                float hi0 = __bfloat162float(qg[(size_t)(d0 + 1) * NTOK + q]) * qs;
                float lo8 = __bfloat162float(qg[(size_t)(d0 + 8) * NTOK + q]) * qs;
                float hi8 = __bfloat162float(qg[(size_t)(d0 + 9) * NTOK + q]) * qs;
                qa[s][kc][rr] = packb(lo0, hi0);
                qa[s][kc][rr + 2] = packb(lo8, hi8);
            }
        }

    float o[2][8][4];
    float o_l[2][4];
#pragma unroll
    for (int s = 0; s < 2; s++) {
#pragma unroll
        for (int i = 0; i < 8; i++)
#pragma unroll
            for (int j = 0; j < 4; j++) o[s][i][j] = 0.f;
#pragma unroll
        for (int j = 0; j < 4; j++) o_l[s][j] = 0.f;
    }

    const int mat = lane >> 3, r = lane & 7;
    const uint32_t kfrag = ksmb + (uint32_t)(((mat & 1) * 8 + r) * 144 + (mat >> 1) * 16);
    const uint32_t vfrag = vsmb + (uint32_t)(r * 144 + mat * 16);

    for (int kt = 0; kt < NKV; kt++) {
        const int st = kt % 3;
        if (kt + 1 < NKV) CP_WAIT1(); else CP_WAIT0();
        __syncthreads();
        if (kt + 2 < NKV) FA_ISSUE((kt + 2) * 64, (kt + 2) % 3);

        const uint32_t kst = kfrag + st * KSTG;
        const uint32_t vst = vfrag + st * KSTG;

        // ---- S = Q^T K + SOFF ----
        float c[2][8][4];
#pragma unroll
        for (int s = 0; s < 2; s++)
#pragma unroll
            for (int nt = 0; nt < 8; nt++)
                c[s][nt][0] = c[s][nt][1] = c[s][nt][2] = c[s][nt][3] = SOFF;
#pragma unroll
        for (int p = 0; p < 4; p++)
#pragma unroll
            for (int kc = 0; kc < 4; kc++) {
                uint32_t kb[4];
                ldsm4t(kb, kst + (uint32_t)(kc * 2304 + p * 32));
                mma_bf16(c[0][2 * p], qa[0][kc], kb[0], kb[1]);
                mma_bf16(c[1][2 * p], qa[1][kc], kb[0], kb[1]);
                mma_bf16(c[0][2 * p + 1], qa[0][kc], kb[2], kb[3]);
                mma_bf16(c[1][2 * p + 1], qa[1][kc], kb[2], kb[3]);
            }

        // ---- ex2 for s=0 -> pa0 ----
        uint32_t pa0[4][4];
        {
            uint32_t pe0[8], pe1[8];
#pragma unroll
            for (int nt = 0; nt < 8; nt++) {
                pe0[nt] = ex2b(c[0][nt][0], c[0][nt][1]);
                pe1[nt] = ex2b(c[0][nt][2], c[0][nt][3]);
            }
#pragma unroll
            for (int mc = 0; mc < 4; mc++) {
                pa0[mc][0] = pe0[2 * mc];
                pa0[mc][1] = pe1[2 * mc];
                pa0[mc][2] = pe0[2 * mc + 1];
                pa0[mc][3] = pe1[2 * mc + 1];
            }
        }
        // l(s=0)
#pragma unroll
        for (int mc = 0; mc < 4; mc++)
            mma_bf16(o_l[0], pa0[mc], lb1, lb1);

        // ---- Block A: PV(s=0) with ex2(s=1) woven between the MMAs ----
        uint32_t qe0[8], qe1[8];
#pragma unroll
        for (int dt = 0; dt < 8; dt++) {
            qe0[dt] = ex2b(c[1][dt][0], c[1][dt][1]);
            uint32_t vb[4];
            ldsm4(vb, vst + (uint32_t)(dt * 1152));
            mma_bf16(o[0][dt], pa0[0], vb[0], vb[1]);
            mma_bf16(o[0][dt], pa0[1], vb[2], vb[3]);
            qe1[dt] = ex2b(c[1][dt][2], c[1][dt][3]);
            uint32_t vb2[4];
            ldsm4(vb2, vst + (uint32_t)(dt * 1152 + 64));
            mma_bf16(o[0][dt], pa0[2], vb2[0], vb2[1]);
            mma_bf16(o[0][dt], pa0[3], vb2[2], vb2[3]);
        }

        // assemble pa1, l(s=1)
        uint32_t pa1[4][4];
#pragma unroll
        for (int mc = 0; mc < 4; mc++) {
            pa1[mc][0] = qe0[2 * mc];
            pa1[mc][1] = qe1[2 * mc];
            pa1[mc][2] = qe0[2 * mc + 1];
            pa1[mc][3] = qe1[2 * mc + 1];
        }
#pragma unroll
        for (int mc = 0; mc < 4; mc++)
            mma_bf16(o_l[1], pa1[mc], lb1, lb1);

        // ---- Block B: PV(s=1) ----
#pragma unroll
        for (int dt = 0; dt < 8; dt++) {
            uint32_t vb[4];
            ldsm4(vb, vst + (uint32_t)(dt * 1152));
            mma_bf16(o[1][dt], pa1[0], vb[0], vb[1]);
            mma_bf16(o[1][dt], pa1[1], vb[2], vb[3]);
            uint32_t vb2[4];
            ldsm4(vb2, vst + (uint32_t)(dt * 1152 + 64));
            mma_bf16(o[1][dt], pa1[2], vb2[0], vb2[1]);
            mma_bf16(o[1][dt], pa1[3], vb2[2], vb2[3]);
        }
    }

    // ---- epilogue ----
    __nv_bfloat16* outp = aoT + (size_t)b * CN + (size_t)(h * HD);
#pragma unroll
    for (int s = 0; s < 2; s++) {
        float l0 = __shfl_sync(0xffffffffu, o_l[s][0], lane & 28);
        float l1 = __shfl_sync(0xffffffffu, o_l[s][2], lane & 28);
        float inv0 = 1.f / l0, inv1 = 1.f / l1;
        int q0 = nq0 + s * 16;
#pragma unroll
        for (int dt = 0; dt < 8; dt++) {
            *(uint32_t*)&outp[(size_t)(q0 + g) * CCH + dt * 8 + tg * 2] =
                packb(o[s][dt][0] * inv0, o[s][dt][1] * inv0);
            *(uint32_t*)&outp[(size_t)(q0 + g + 8) * CCH + dt * 8 + tg * 2] =
                packb(o[s][dt][2] * inv1, o[s][dt][3] * inv1);
        }
    }
}

// ---------------- launch ------------------------------------------------------
extern "C" void kernel_launch(void* const* d_in, const int* in_sizes, int n_in,
                              void* d_out, int out_size) {
    const float* x      = (const float*)d_in[0];
    const float* norm_w = (const float*)d_in[1];
    const float* norm_b = (const float*)d_in[2];
    const float* qkv_w  = (const float*)d_in[3];
    const float* qkv_b  = (const float*)d_in[4];
    const float* proj_w = (const float*)d_in[5];
    const float* proj_b = (const float*)d_in[6];
    float* out = (float*)d_out;

    __nv_bfloat16 *hn, *qkv, *aoT, *qkvwb, *projwb;
    cudaGetSymbolAddress((void**)&hn,     g_hn);
    cudaGetSymbolAddress((void**)&qkv,    g_qkv);
    cudaGetSymbolAddress((void**)&aoT,    g_aoT);
    cudaGetSymbolAddress((void**)&qkvwb,  g_qkvwb);
    cudaGetSymbolAddress((void**)&projwb, g_projwb);

    const size_t CN = (size_t)CCH * NTOK;

    const int SM_G0 = 3 * (ASTG + BSTG0);  // 56832
    const int SM_G1 = 3 * (ASTG + BSTG1);  // 61440
    const int SM_FA = 6 * KSTG;            // 55296
    static int attr_done = 0;
    if (!attr_done) {
        cudaFuncSetAttribute(gemm3<0>, cudaFuncAttributeMaxDynamicSharedMemorySize, SM_G0);
        cudaFuncSetAttribute(gemm3<1>, cudaFuncAttributeMaxDynamicSharedMemorySize, SM_G1);
        cudaFuncSetAttribute(flash_attn, cudaFuncAttributeMaxDynamicSharedMemorySize, SM_FA);
        attr_done = 1;
    }

    // 0) weight fp32 -> bf16
    cvt_w<<<(3 * CCH * CCH + CCH * CCH) / 4 / 256, 256>>>(qkv_w, proj_w);

    // 1) GroupNorm (fused, writes bf16 hn)
    gn_fused<<<BATCH * GROUPS, 512>>>(x, norm_w, norm_b);

    // 2) QKV GEMM: bf16 W [1536,512] x hn [512,4096] -> bf16 qkv
    gemm3<0><<<dim3(NTOK / 128, (3 * CCH) / 128, BATCH), 256, SM_G0>>>(
        qkvwb, hn, qkv, CCH, NTOK, NTOK,
        CN, 3 * CN, qkv_b, nullptr, 0);

    // 3) fused attention (static-max, MUFU/tensor interleave)
    flash_attn<<<dim3(NTOK / 128, NH, BATCH), 128, SM_FA>>>(qkv, aoT);

    // 4) proj + bias + residual -> fp32 out
    gemm3<1><<<dim3(NTOK / 128, CCH / 128, BATCH), 256, SM_G1>>>(
        projwb, aoT, out, CCH, CCH, NTOK,
        CN, CN, proj_b, x, CN);
}